// round 16
// baseline (speedup 1.0000x reference)
#include <cuda_runtime.h>
#include <cstdint>

#define N_NODES 100000
#define D       128
#define R       4
#define E       500000
#define RN      (R * N_NODES)   // 400000
#define REDGES  (R * E)         // 2000000
#define NB      782             // scan blocks (512 each)
#define NTILE   782             // ceil(N_NODES/128)

// ---------------- scratch (static device globals; no runtime allocs) ----------
__device__ float g_neigh[(size_t)R * N_NODES * D];   // mean-aggregated neighbors
__device__ int   g_cnti[RN];
__device__ int   g_off[RN];      // local exclusive within 512-chunk; fill bumps
__device__ int   g_bsum[1024];
__device__ int   g_bscan[1024];  // exclusive scan of 512-chunk sums
__device__ int   g_esrc[REDGES];
__device__ float g_Wt[(R + 1) * D * D];   // [seg][k][n], scaled
__device__ float g_bavg[D];
__device__ int   g_scan_ctr;

// =================== helpers ====================================================
__device__ __forceinline__ uint32_t f2tf32(float f) {
    uint32_t u;
    asm("cvt.rna.tf32.f32 %0, %1;" : "=r"(u) : "f"(f));
    return u;
}
__device__ __forceinline__ void mma8(float* c, const uint32_t* a, const uint32_t* b) {
    asm volatile(
        "mma.sync.aligned.m16n8k8.row.col.f32.tf32.tf32.f32 "
        "{%0,%1,%2,%3}, {%4,%5,%6,%7}, {%8,%9}, {%0,%1,%2,%3};"
        : "+f"(c[0]), "+f"(c[1]), "+f"(c[2]), "+f"(c[3])
        : "r"(a[0]), "r"(a[1]), "r"(a[2]), "r"(a[3]), "r"(b[0]), "r"(b[1]));
}
__device__ __forceinline__ uint32_t smem_u32(const void* p) {
    uint32_t a;
    asm("{ .reg .u64 t; cvta.to.shared.u64 t, %1; cvt.u32.u64 %0, t; }" : "=r"(a) : "l"(p));
    return a;
}
__device__ __forceinline__ void cp16(uint32_t dst, const void* src, bool ok) {
    int sz = ok ? 16 : 0;
    asm volatile("cp.async.cg.shared.global [%0], [%1], 16, %2;"
                 :: "r"(dst), "l"(src), "r"(sz) : "memory");
}
#define CP_COMMIT() asm volatile("cp.async.commit_group;" ::: "memory")
#define CP_WAIT(n)  asm volatile("cp.async.wait_group %0;" :: "n"(n) : "memory")

// ---------------- zero counts + combine weights + reset scan counter -----------
__global__ __launch_bounds__(256) void zc_kernel(const float* __restrict__ Ws,
                                                 const float* __restrict__ Wn,
                                                 const float* __restrict__ b) {
    int i = blockIdx.x * blockDim.x + threadIdx.x;
    if (i == 0) g_scan_ctr = 0;
    if (i < RN) g_cnti[i] = 0;
    if (i < (R + 1) * D * D) {
        int seg = i >> 14, rem = i & 16383;
        float v;
        if (seg == 0) {
            v = 0.f;
            #pragma unroll
            for (int r = 0; r < R; r++) v += Ws[r * D * D + rem];
            v *= 0.25f;
        } else {
            v = Wn[(seg - 1) * D * D + rem] * 0.25f;
        }
        g_Wt[i] = v;
    }
    if (i < D) {
        float s = 0.f;
        #pragma unroll
        for (int r = 0; r < R; r++) s += b[r * D + i];
        g_bavg[i] = s * 0.25f;
    }
}

// ---------------- CSR build (count/fill: 2 edges per thread) -------------------
__global__ __launch_bounds__(256) void count_kernel(const int* __restrict__ dst) {
    int i = (blockIdx.x * blockDim.x + threadIdx.x) * 2;
    if (i >= REDGES) return;
    int2 d2 = *(const int2*)(dst + i);
    int r = i / E;
    atomicAdd(&g_cnti[r * N_NODES + d2.x], 1);
    atomicAdd(&g_cnti[r * N_NODES + d2.y], 1);
}

// scan1 + scan2 fused: per-block exclusive scan; last block scans block sums.
__global__ __launch_bounds__(512) void scan12_kernel() {
    __shared__ int tmp[512];
    __shared__ int sdata[NB];
    __shared__ int islast;
    int t = threadIdx.x, lane = t & 31;
    int i = blockIdx.x * 512 + t;
    int v = (i < RN) ? g_cnti[i] : 0;
    tmp[t] = v;
    __syncthreads();
    for (int o = 1; o < 512; o <<= 1) {
        int a = (t >= o) ? tmp[t - o] : 0;
        __syncthreads();
        tmp[t] += a;
        __syncthreads();
    }
    if (i < RN) g_off[i] = tmp[t] - v;
    if (t == 511) {
        g_bsum[blockIdx.x] = tmp[511];
        __threadfence();
        int prev = atomicAdd(&g_scan_ctr, 1);
        islast = (prev == NB - 1);
    }
    __syncthreads();
    if (!islast) return;
    __threadfence();
    for (int j = t; j < NB; j += 512) sdata[j] = g_bsum[j];
    __syncthreads();
    if (t < 32) {
        int start = lane * 25;
        int sum = 0;
        #pragma unroll 1
        for (int j = 0; j < 25; j++) {
            int idx = start + j;
            if (idx < NB) { int x = sdata[idx]; sdata[idx] = sum; sum += x; }
        }
        int vv = sum;
        #pragma unroll
        for (int o = 1; o < 32; o <<= 1) {
            int n = __shfl_up_sync(0xffffffffu, vv, o);
            if (lane >= o) vv += n;
        }
        int excl = vv - sum;
        #pragma unroll 1
        for (int j = 0; j < 25; j++) {
            int idx = start + j;
            if (idx < NB) g_bscan[idx] = sdata[idx] + excl;
        }
    }
}

__global__ __launch_bounds__(256) void fill_kernel(const int* __restrict__ src,
                                                   const int* __restrict__ dst) {
    int i = (blockIdx.x * blockDim.x + threadIdx.x) * 2;
    if (i >= REDGES) return;
    int2 d2 = *(const int2*)(dst + i);
    int2 s2 = *(const int2*)(src + i);
    int r = i / E;
    int rd0 = r * N_NODES + d2.x;
    int rd1 = r * N_NODES + d2.y;
    int p0 = atomicAdd(&g_off[rd0], 1) + g_bscan[rd0 >> 9];
    int p1 = atomicAdd(&g_off[rd1], 1) + g_bscan[rd1 >> 9];
    g_esrc[p0] = s2.x;
    g_esrc[p1] = s2.y;
}

// ---------------- aggregate: warp per node, loop relations (R11 v1) ------------
__global__ __launch_bounds__(256) void aggregate_kernel(const float* __restrict__ x) {
    int w = (int)(((size_t)blockIdx.x * blockDim.x + threadIdx.x) >> 5);
    int lane = threadIdx.x & 31;
    if (w >= N_NODES) return;

    #pragma unroll
    for (int r = 0; r < R; r++) {
        int rd = r * N_NODES + w;
        int cdeg = g_cnti[rd];
        int base = g_off[rd] + g_bscan[rd >> 9] - cdeg;
        float4 s0 = make_float4(0.f, 0.f, 0.f, 0.f);
        float4 s1 = make_float4(0.f, 0.f, 0.f, 0.f);
        int e = 0;
        for (; e + 2 <= cdeg; e += 2) {
            int sa = g_esrc[base + e];
            int sb = g_esrc[base + e + 1];
            float4 va = *(const float4*)(x + (size_t)sa * D + lane * 4);
            float4 vb = *(const float4*)(x + (size_t)sb * D + lane * 4);
            s0.x += va.x; s0.y += va.y; s0.z += va.z; s0.w += va.w;
            s1.x += vb.x; s1.y += vb.y; s1.z += vb.z; s1.w += vb.w;
        }
        if (e < cdeg) {
            int sa = g_esrc[base + e];
            float4 va = *(const float4*)(x + (size_t)sa * D + lane * 4);
            s0.x += va.x; s0.y += va.y; s0.z += va.z; s0.w += va.w;
        }
        float ic = 1.f / fmaxf((float)cdeg, 1.f);
        float4 o;
        o.x = (s0.x + s1.x) * ic;
        o.y = (s0.y + s1.y) * ic;
        o.z = (s0.z + s1.z) * ic;
        o.w = (s0.w + s1.w) * ic;
        *(float4*)(g_neigh + (size_t)rd * D + lane * 4) = o;
    }
}

// ---------------- tf32 GEMM: R4 config + 2-stage cp.async staging --------------
// 128 threads, 4 warps 2x2, warp tile 64x64. Raw fp32 stages:
//   A [128][36] f32 (18432 B)  — frag banks (4*qid+kid) conflict-free
//   B [32][132] f32 (16896 B)  — frag banks (4*kid+qid) conflict-free
// cvt.rna.tf32 after fragment LDS (identical rounding to prior rounds).
#define A_STRIDE 36
#define B_STRIDE 132
#define A_BYTES  (128 * A_STRIDE * 4)      // 18432
#define STAGE_B  (A_BYTES + 32 * B_STRIDE * 4)   // 35328
#define SM_GEMM  (2 * STAGE_B)             // 70656

__global__ __launch_bounds__(128) void gemm_kernel(const float* __restrict__ x,
                                                   float* __restrict__ out) {
    extern __shared__ char smem[];
    uint32_t sbase = smem_u32(smem);

    int tid  = threadIdx.x;
    int wid  = tid >> 5, lane = tid & 31;
    int qid  = lane >> 2, kid = lane & 3;
    int wm   = wid & 1, wn = wid >> 1;
    int row0 = blockIdx.x * 128;

    float c[4][8][4];
    #pragma unroll
    for (int mt = 0; mt < 4; mt++)
        #pragma unroll
        for (int nt = 0; nt < 8; nt++)
            #pragma unroll
            for (int j = 0; j < 4; j++) c[mt][nt][j] = 0.f;

    // copy slots: A -> thread t handles row t (8 cp16); B -> row t>>2, part t&3
    int nA   = row0 + tid;
    bool okA = (nA < N_NODES);
    int rB   = tid >> 2, pB = tid & 3;

    auto issue_chunk = [&](int ch, int st) {
        int seg = ch >> 2, k0 = (ch & 3) * 32;
        const float* Abase = (seg == 0) ? x
                           : (g_neigh + (size_t)(seg - 1) * N_NODES * D);
        const float* asrc = Abase + (size_t)(okA ? nA : 0) * D + k0;
        uint32_t adst = sbase + st * STAGE_B + tid * (A_STRIDE * 4);
        #pragma unroll
        for (int j = 0; j < 8; j++)
            cp16(adst + j * 16, asrc + j * 4, okA);

        const float* bsrc = g_Wt + seg * D * D + (size_t)(k0 + rB) * D + pB * 32;
        uint32_t bdst = sbase + st * STAGE_B + A_BYTES + rB * (B_STRIDE * 4) + pB * 128;
        #pragma unroll
        for (int j = 0; j < 8; j++)
            cp16(bdst + j * 16, bsrc + j * 4, true);
        CP_COMMIT();
    };

    issue_chunk(0, 0);

    #pragma unroll 1
    for (int ch = 0; ch < 20; ch++) {
        int st = ch & 1;
        if (ch + 1 < 20) {
            issue_chunk(ch + 1, st ^ 1);
            CP_WAIT(1);            // chunk ch complete; ch+1 in flight
        } else {
            CP_WAIT(0);
        }
        __syncthreads();

        const float* As = (const float*)(smem + st * STAGE_B);
        const float* Bs = (const float*)(smem + st * STAGE_B + A_BYTES);

        #pragma unroll
        for (int kk8 = 0; kk8 < 4; kk8++) {
            int k8 = kk8 * 8;
            uint32_t a[4][4], b[8][2];
            #pragma unroll
            for (int mt = 0; mt < 4; mt++) {
                int row = wm * 64 + mt * 16 + qid;
                a[mt][0] = f2tf32(As[row * A_STRIDE + k8 + kid]);
                a[mt][1] = f2tf32(As[(row + 8) * A_STRIDE + k8 + kid]);
                a[mt][2] = f2tf32(As[row * A_STRIDE + k8 + 4 + kid]);
                a[mt][3] = f2tf32(As[(row + 8) * A_STRIDE + k8 + 4 + kid]);
            }
            #pragma unroll
            for (int nt = 0; nt < 8; nt++) {
                int col = wn * 64 + nt * 8 + qid;
                b[nt][0] = f2tf32(Bs[(k8 + kid) * B_STRIDE + col]);
                b[nt][1] = f2tf32(Bs[(k8 + 4 + kid) * B_STRIDE + col]);
            }
            #pragma unroll
            for (int mt = 0; mt < 4; mt++)
                #pragma unroll
                for (int nt = 0; nt < 8; nt++)
                    mma8(c[mt][nt], a[mt], b[nt]);
        }

        __syncthreads();   // readers done before this stage is refilled at ch+2
    }

    // ---- epilogue: add mean bias, store float2 pairs ----
    #pragma unroll
    for (int mt = 0; mt < 4; mt++) {
        int r0q = row0 + wm * 64 + mt * 16 + qid;
        #pragma unroll
        for (int nt = 0; nt < 8; nt++) {
            int col = wn * 64 + nt * 8 + kid * 2;
            float b0 = g_bavg[col], b1 = g_bavg[col + 1];
            if (r0q < N_NODES) {
                float2 o = make_float2(c[mt][nt][0] + b0, c[mt][nt][1] + b1);
                *(float2*)(out + (size_t)r0q * D + col) = o;
            }
            if (r0q + 8 < N_NODES) {
                float2 o = make_float2(c[mt][nt][2] + b0, c[mt][nt][3] + b1);
                *(float2*)(out + (size_t)(r0q + 8) * D + col) = o;
            }
        }
    }
}

// ---------------- launch --------------------------------------------------------
extern "C" void kernel_launch(void* const* d_in, const int* in_sizes, int n_in,
                              void* d_out, int out_size) {
    const float* x      = (const float*)d_in[0];
    const int*   src    = (const int*)d_in[1];
    const int*   dst    = (const int*)d_in[2];
    const float* Wself  = (const float*)d_in[3];
    const float* Wneigh = (const float*)d_in[4];
    const float* b      = (const float*)d_in[5];
    float* out = (float*)d_out;

    zc_kernel<<<(RN + 255) / 256, 256>>>(Wself, Wneigh, b);       // 0
    count_kernel<<<(REDGES / 2 + 255) / 256, 256>>>(dst);         // 1
    scan12_kernel<<<NB, 512>>>();                                 // 2
    fill_kernel<<<(REDGES / 2 + 255) / 256, 256>>>(src, dst);     // 3 <- profiled
    aggregate_kernel<<<(N_NODES * 32 + 255) / 256, 256>>>(x);     // 4

    cudaFuncSetAttribute(gemm_kernel, cudaFuncAttributeMaxDynamicSharedMemorySize, SM_GEMM);
    gemm_kernel<<<NTILE, 128, SM_GEMM>>>(x, out);                 // 5
    (void)in_sizes; (void)n_in; (void)out_size;
}

// round 17
// speedup vs baseline: 1.2266x; 1.2266x over previous
#include <cuda_runtime.h>
#include <cuda_fp16.h>
#include <cstdint>

#define N_NODES 100000
#define D       128
#define R       4
#define E       500000
#define RN      (R * N_NODES)   // 400000
#define REDGES  (R * E)         // 2000000
#define NB      782             // scan blocks (512 each)
#define NTILE   782             // ceil(N_NODES/128)

// ---------------- scratch (static device globals; no runtime allocs) ----------
__device__ __half g_neigh[(size_t)R * N_NODES * D];  // fp16 neigh (102.4 MB)
__device__ int    g_cnti[RN];
__device__ int    g_off[RN];     // local exclusive within 512-chunk; fill bumps
__device__ int    g_bsum[1024];
__device__ int    g_bscan[1024]; // exclusive scan of 512-chunk sums
__device__ int    g_esrc[REDGES];
__device__ float  g_Wt[(R + 1) * D * D];  // [seg][k][n], scaled
__device__ float  g_bavg[D];
__device__ int    g_scan_ctr;

// =================== helpers ====================================================
__device__ __forceinline__ uint32_t f2tf32(float f) {
    uint32_t u;
    asm("cvt.rna.tf32.f32 %0, %1;" : "=r"(u) : "f"(f));
    return u;
}
__device__ __forceinline__ void mma8(float* c, const uint32_t* a, const uint32_t* b) {
    asm volatile(
        "mma.sync.aligned.m16n8k8.row.col.f32.tf32.tf32.f32 "
        "{%0,%1,%2,%3}, {%4,%5,%6,%7}, {%8,%9}, {%0,%1,%2,%3};"
        : "+f"(c[0]), "+f"(c[1]), "+f"(c[2]), "+f"(c[3])
        : "r"(a[0]), "r"(a[1]), "r"(a[2]), "r"(a[3]), "r"(b[0]), "r"(b[1]));
}

// ---------------- zero counts + combine weights + reset scan counter -----------
__global__ __launch_bounds__(256) void zc_kernel(const float* __restrict__ Ws,
                                                 const float* __restrict__ Wn,
                                                 const float* __restrict__ b) {
    int i = blockIdx.x * blockDim.x + threadIdx.x;
    if (i == 0) g_scan_ctr = 0;
    if (i < RN) g_cnti[i] = 0;
    if (i < (R + 1) * D * D) {
        int seg = i >> 14, rem = i & 16383;
        float v;
        if (seg == 0) {
            v = 0.f;
            #pragma unroll
            for (int r = 0; r < R; r++) v += Ws[r * D * D + rem];
            v *= 0.25f;
        } else {
            v = Wn[(seg - 1) * D * D + rem] * 0.25f;
        }
        g_Wt[i] = v;
    }
    if (i < D) {
        float s = 0.f;
        #pragma unroll
        for (int r = 0; r < R; r++) s += b[r * D + i];
        g_bavg[i] = s * 0.25f;
    }
}

// ---------------- CSR build (count/fill: 2 edges per thread) -------------------
__global__ __launch_bounds__(256) void count_kernel(const int* __restrict__ dst) {
    int i = (blockIdx.x * blockDim.x + threadIdx.x) * 2;
    if (i >= REDGES) return;
    int2 d2 = *(const int2*)(dst + i);
    int r = i / E;               // pair never straddles a relation boundary (E even)
    atomicAdd(&g_cnti[r * N_NODES + d2.x], 1);
    atomicAdd(&g_cnti[r * N_NODES + d2.y], 1);
}

// scan1 + scan2 fused: per-block exclusive scan; last block scans block sums.
__global__ __launch_bounds__(512) void scan12_kernel() {
    __shared__ int tmp[512];
    __shared__ int sdata[NB];
    __shared__ int islast;
    int t = threadIdx.x, lane = t & 31;
    int i = blockIdx.x * 512 + t;
    int v = (i < RN) ? g_cnti[i] : 0;
    tmp[t] = v;
    __syncthreads();
    for (int o = 1; o < 512; o <<= 1) {
        int a = (t >= o) ? tmp[t - o] : 0;
        __syncthreads();
        tmp[t] += a;
        __syncthreads();
    }
    if (i < RN) g_off[i] = tmp[t] - v;
    if (t == 511) {
        g_bsum[blockIdx.x] = tmp[511];
        __threadfence();
        int prev = atomicAdd(&g_scan_ctr, 1);
        islast = (prev == NB - 1);
    }
    __syncthreads();
    if (!islast) return;
    __threadfence();
    for (int j = t; j < NB; j += 512) sdata[j] = g_bsum[j];
    __syncthreads();
    if (t < 32) {
        int start = lane * 25;
        int sum = 0;
        #pragma unroll 1
        for (int j = 0; j < 25; j++) {
            int idx = start + j;
            if (idx < NB) { int x = sdata[idx]; sdata[idx] = sum; sum += x; }
        }
        int vv = sum;
        #pragma unroll
        for (int o = 1; o < 32; o <<= 1) {
            int n = __shfl_up_sync(0xffffffffu, vv, o);
            if (lane >= o) vv += n;
        }
        int excl = vv - sum;
        #pragma unroll 1
        for (int j = 0; j < 25; j++) {
            int idx = start + j;
            if (idx < NB) g_bscan[idx] = sdata[idx] + excl;
        }
    }
}

__global__ __launch_bounds__(256) void fill_kernel(const int* __restrict__ src,
                                                   const int* __restrict__ dst) {
    int i = (blockIdx.x * blockDim.x + threadIdx.x) * 2;
    if (i >= REDGES) return;
    int2 d2 = *(const int2*)(dst + i);
    int2 s2 = *(const int2*)(src + i);
    int r = i / E;
    int rd0 = r * N_NODES + d2.x;
    int rd1 = r * N_NODES + d2.y;
    int p0 = atomicAdd(&g_off[rd0], 1) + g_bscan[rd0 >> 9];
    int p1 = atomicAdd(&g_off[rd1], 1) + g_bscan[rd1 >> 9];
    g_esrc[p0] = s2.x;
    g_esrc[p1] = s2.y;
}

// ---------------- aggregate: warp per node, loop relations; fp16 stores --------
__global__ __launch_bounds__(256) void aggregate_kernel(const float* __restrict__ x) {
    int w = (int)(((size_t)blockIdx.x * blockDim.x + threadIdx.x) >> 5);
    int lane = threadIdx.x & 31;
    if (w >= N_NODES) return;

    #pragma unroll
    for (int r = 0; r < R; r++) {
        int rd = r * N_NODES + w;
        int cdeg = g_cnti[rd];
        int base = g_off[rd] + g_bscan[rd >> 9] - cdeg;
        float4 s0 = make_float4(0.f, 0.f, 0.f, 0.f);
        float4 s1 = make_float4(0.f, 0.f, 0.f, 0.f);
        int e = 0;
        for (; e + 2 <= cdeg; e += 2) {
            int sa = g_esrc[base + e];
            int sb = g_esrc[base + e + 1];
            float4 va = *(const float4*)(x + (size_t)sa * D + lane * 4);
            float4 vb = *(const float4*)(x + (size_t)sb * D + lane * 4);
            s0.x += va.x; s0.y += va.y; s0.z += va.z; s0.w += va.w;
            s1.x += vb.x; s1.y += vb.y; s1.z += vb.z; s1.w += vb.w;
        }
        if (e < cdeg) {
            int sa = g_esrc[base + e];
            float4 va = *(const float4*)(x + (size_t)sa * D + lane * 4);
            s0.x += va.x; s0.y += va.y; s0.z += va.z; s0.w += va.w;
        }
        float ic = 1.f / fmaxf((float)cdeg, 1.f);
        __half2 h0 = __floats2half2_rn((s0.x + s1.x) * ic, (s0.y + s1.y) * ic);
        __half2 h1 = __floats2half2_rn((s0.z + s1.z) * ic, (s0.w + s1.w) * ic);
        uint2 pk;
        pk.x = *(uint32_t*)&h0;
        pk.y = *(uint32_t*)&h1;
        *(uint2*)(g_neigh + (size_t)rd * D + lane * 4) = pk;   // 8B store
    }
}

// ---------------- tf32 mma.sync GEMM (frozen config; fp16 neigh loads) ---------
// Block tile 128x128, 128 threads = 4 warps in 2x2, warp tile 64x64.
__global__ __launch_bounds__(128) void gemm_kernel(const float* __restrict__ x,
                                                   float* __restrict__ out) {
    __shared__ uint32_t As[32][136];
    __shared__ uint32_t Bs[32][136];

    int tid  = threadIdx.x;
    int wid  = tid >> 5, lane = tid & 31;
    int qid  = lane >> 2, kid = lane & 3;
    int wm   = wid & 1, wn = wid >> 1;
    int row0 = blockIdx.x * 128;

    float c[4][8][4];
    #pragma unroll
    for (int mt = 0; mt < 4; mt++)
        #pragma unroll
        for (int nt = 0; nt < 8; nt++)
            #pragma unroll
            for (int j = 0; j < 4; j++) c[mt][nt][j] = 0.f;

    #pragma unroll 1
    for (int seg = 0; seg < R + 1; seg++) {
        const float*  Bsrc = g_Wt + seg * D * D;
        const __half* Hsrc = g_neigh + (size_t)(seg - 1) * N_NODES * D;  // seg>=1

        #pragma unroll 1
        for (int k0 = 0; k0 < D; k0 += 32) {
            __syncthreads();
            // ---- A chunk: 128 rows x 32 k -> transposed+swizzled ----
            #pragma unroll
            for (int p = 0; p < 8; p++) {
                int q = tid + p * 128;
                int row = q >> 3, kq = q & 7;
                int n = row0 + row;
                float f4[4] = {0.f, 0.f, 0.f, 0.f};
                if (n < N_NODES) {
                    if (seg == 0) {
                        float4 v = *(const float4*)(x + (size_t)n * D + k0 + kq * 4);
                        f4[0] = v.x; f4[1] = v.y; f4[2] = v.z; f4[3] = v.w;
                    } else {
                        uint2 pk = *(const uint2*)(Hsrc + (size_t)n * D + k0 + kq * 4);
                        __half2 h0 = *(__half2*)&pk.x;
                        __half2 h1 = *(__half2*)&pk.y;
                        float2 a0 = __half22float2(h0);
                        float2 a1 = __half22float2(h1);
                        f4[0] = a0.x; f4[1] = a0.y; f4[2] = a1.x; f4[3] = a1.y;
                    }
                }
                #pragma unroll
                for (int i = 0; i < 4; i++) {
                    int k = kq * 4 + i;
                    As[k][row ^ (((k >> 2) & 3) << 3)] = f2tf32(f4[i]);
                }
            }
            // ---- B chunk: 32 k-rows x 128 n ----
            #pragma unroll
            for (int p = 0; p < 8; p++) {
                int q = tid + p * 128;
                int kk = q >> 5, nq = q & 31;
                float4 v = *(const float4*)(Bsrc + (size_t)(k0 + kk) * D + nq * 4);
                uint4 u;
                u.x = f2tf32(v.x); u.y = f2tf32(v.y); u.z = f2tf32(v.z); u.w = f2tf32(v.w);
                *(uint4*)&Bs[kk][nq * 4] = u;
            }
            __syncthreads();
            // ---- 4 k8-steps ----
            #pragma unroll
            for (int kk8 = 0; kk8 < 4; kk8++) {
                int k8 = kk8 * 8;
                int C0 = ((2 * kk8) & 3) << 3;
                int C1 = ((2 * kk8 + 1) & 3) << 3;
                uint32_t a[4][4], b[8][2];
                #pragma unroll
                for (int mt = 0; mt < 4; mt++) {
                    int row = wm * 64 + mt * 16 + qid;
                    a[mt][0] = As[k8 + kid][row ^ C0];
                    a[mt][1] = As[k8 + kid][(row + 8) ^ C0];
                    a[mt][2] = As[k8 + 4 + kid][row ^ C1];
                    a[mt][3] = As[k8 + 4 + kid][(row + 8) ^ C1];
                }
                #pragma unroll
                for (int nt = 0; nt < 8; nt++) {
                    int col = wn * 64 + nt * 8 + qid;
                    b[nt][0] = Bs[k8 + kid][col];
                    b[nt][1] = Bs[k8 + 4 + kid][col];
                }
                #pragma unroll
                for (int mt = 0; mt < 4; mt++)
                    #pragma unroll
                    for (int nt = 0; nt < 8; nt++)
                        mma8(c[mt][nt], a[mt], b[nt]);
            }
        }
    }

    // ---- epilogue: add mean bias, store float2 pairs ----
    #pragma unroll
    for (int mt = 0; mt < 4; mt++) {
        int r0q = row0 + wm * 64 + mt * 16 + qid;
        #pragma unroll
        for (int nt = 0; nt < 8; nt++) {
            int col = wn * 64 + nt * 8 + kid * 2;
            float b0 = g_bavg[col], b1 = g_bavg[col + 1];
            if (r0q < N_NODES) {
                float2 o = make_float2(c[mt][nt][0] + b0, c[mt][nt][1] + b1);
                *(float2*)(out + (size_t)r0q * D + col) = o;
            }
            if (r0q + 8 < N_NODES) {
                float2 o = make_float2(c[mt][nt][2] + b0, c[mt][nt][3] + b1);
                *(float2*)(out + (size_t)(r0q + 8) * D + col) = o;
            }
        }
    }
}

// ---------------- launch --------------------------------------------------------
extern "C" void kernel_launch(void* const* d_in, const int* in_sizes, int n_in,
                              void* d_out, int out_size) {
    const float* x      = (const float*)d_in[0];
    const int*   src    = (const int*)d_in[1];
    const int*   dst    = (const int*)d_in[2];
    const float* Wself  = (const float*)d_in[3];
    const float* Wneigh = (const float*)d_in[4];
    const float* b      = (const float*)d_in[5];
    float* out = (float*)d_out;

    zc_kernel<<<(RN + 255) / 256, 256>>>(Wself, Wneigh, b);       // 0
    count_kernel<<<(REDGES / 2 + 255) / 256, 256>>>(dst);         // 1
    scan12_kernel<<<NB, 512>>>();                                 // 2
    fill_kernel<<<(REDGES / 2 + 255) / 256, 256>>>(src, dst);     // 3 <- profiled
    aggregate_kernel<<<(N_NODES * 32 + 255) / 256, 256>>>(x);     // 4
    gemm_kernel<<<NTILE, 128>>>(x, out);                          // 5
    (void)in_sizes; (void)n_in; (void)out_size;
}